// round 5
// baseline (speedup 1.0000x reference)
#include <cuda_runtime.h>

// InterConv: B=2048, F=39, E=64, C=64, P=741
// out[b, c*P + p] = relu( U[c][ii[p]] + V[c][jj[p]] ),  U = x@Wi^T + bias, V = x@Wj^T
//
// smem overlay (45.3 KB, 4 CTAs/SM):
//   phase 0/1: A = xs [0,2624)   B = Wi [2624,6976) + Wj [6976,11328)
//   phase 2:   A = Uc [0,2624)   B = VI [2624,5504) + tab16 [5504,5876) + tabc [5876,7356)

#define FN 39
#define EN 64
#define CN 64
#define PN 741            // 39*38/2
#define OUTB (CN * PN)    // 47424 floats per batch
#define THREADS 256

#define A_OFF   0
#define B_OFF   2624
#define VI_OFF  B_OFF                 // V interleaved: [c][45]  (VI[c][ (j&3)*11 + (j>>2) ])
#define T16_OFF (B_OFF + CN*45)       // u16 base table, 741 entries (372 floats)
#define TC_OFF  (T16_OFF + 372)       // u64 packed table, 4 copies x 185 (1480 floats)
#define SMEM_FLOATS 11328
#define SMEM_BYTES  (SMEM_FLOATS * 4)

// packed fp32x2 FMA (Blackwell; exact fp32 semantics, 2x FFMA throughput)
#define FMA_F32X2(acc, a, b) \
    asm("fma.rn.f32x2 %0, %1, %2, %0;" : "+l"(acc) : "l"(a), "l"(b))

// tab entry: low byte = i*4 (byte offset into Uc row), high byte = vi_idx(j)*4
__device__ __forceinline__ unsigned tab_entry(int i, int j) {
    return (unsigned)(i * 4) | ((unsigned)((((j & 3) * 11) + (j >> 2)) * 4) << 8);
}

extern __shared__ float smem[];

__global__ void __launch_bounds__(THREADS, 4)
interconv_kernel(const float* __restrict__ x,
                 const float* __restrict__ W,
                 const float* __restrict__ bias,
                 float* __restrict__ out)
{
    const int tid = threadIdx.x;
    const long long b = blockIdx.x;

    // ---- Phase 0: stage x and W (float4) ---------------------------------
    {
        float4* xs4 = (float4*)(smem + A_OFF);
        const float4* xb4 = (const float4*)(x + b * (long long)(FN * EN));
        #pragma unroll
        for (int it = 0; it < 3; it++) {
            int idx = tid + it * THREADS;
            if (idx < (FN * EN) / 4) xs4[idx] = xb4[idx];
        }
        if (tid < EN)                              // zero pad row f=39
            smem[A_OFF + FN * EN + tid] = 0.f;

        // W gmem: [c][128] floats (k=0 -> Wi, k=1 -> Wj); smem stride 17 float4
        float4* Wi4 = (float4*)(smem + B_OFF);
        float4* Wj4 = Wi4 + CN * 17;
        const float4* Wg4 = (const float4*)W;
        #pragma unroll
        for (int it = 0; it < 8; it++) {
            int idx = tid + it * THREADS;          // 2048 float4 total
            int c = idx >> 5, q = idx & 31;
            float4 w = Wg4[idx];
            if (q < 16) Wi4[c * 17 + q] = w;
            else        Wj4[c * 17 + (q - 16)] = w;
        }
    }
    __syncthreads();

    // ---- Phase 1: U = x @ Wi^T + b, V = x @ Wj^T  (f32x2, regs only) -----
    const int c  = tid & 63;
    const int fg = tid >> 6;

    unsigned long long au[10], av[10];
    #pragma unroll
    for (int k = 0; k < 10; k++) { au[k] = 0ull; av[k] = 0ull; }

    {
        const ulonglong2* xs2 = (const ulonglong2*)(smem + A_OFF);   // [f][16]
        const ulonglong2* Wi2 = (const ulonglong2*)(smem + B_OFF);   // [c][17]
        const ulonglong2* Wj2 = Wi2 + CN * 17;

        #pragma unroll
        for (int e4 = 0; e4 < 16; e4++) {
            ulonglong2 wi = Wi2[c * 17 + e4];
            ulonglong2 wj = Wj2[c * 17 + e4];
            #pragma unroll
            for (int k = 0; k < 10; k++) {
                ulonglong2 xv = xs2[(fg + 4 * k) * 16 + e4];  // f=39 row is zeros
                FMA_F32X2(au[k], xv.x, wi.x);
                FMA_F32X2(au[k], xv.y, wi.y);
                FMA_F32X2(av[k], xv.x, wj.x);
                FMA_F32X2(av[k], xv.y, wj.y);
            }
        }
    }
    __syncthreads();   // all xs/W reads done; safe to overlay

    // ---- Phase 1b: write Uc / VI (interleaved) + build tables -----------
    float* Uc = smem + A_OFF;                    // [c][41]
    float* VI = smem + VI_OFF;                   // [c][45], idx = (f&3)*11 + (f>>2)
    unsigned short* tab16 = (unsigned short*)(smem + T16_OFF);
    unsigned long long* tabc = (unsigned long long*)(smem + TC_OFF);

    {
        const float bc = __ldg(bias + c);
        #pragma unroll
        for (int k = 0; k < 10; k++) {
            int f = fg + 4 * k;                  // f<=39 (f=39 lands in pads)
            float ulo = __uint_as_float((unsigned)au[k]);
            float uhi = __uint_as_float((unsigned)(au[k] >> 32));
            float vlo = __uint_as_float((unsigned)av[k]);
            float vhi = __uint_as_float((unsigned)(av[k] >> 32));
            Uc[c * 41 + f] = ulo + uhi + bc;     // bias folded into U
            VI[c * 45 + (f & 3) * 11 + (f >> 2)] = vlo + vhi;
        }

        // base u16 table (for head/tail scalar paths)
        for (int p = tid; p < PN; p += THREADS) {
            int i = 0, rem = p;
            while (rem >= FN - 1 - i) { rem -= FN - 1 - i; i++; }
            int j = i + 1 + rem;
            tab16[p] = (unsigned short)tab_entry(i, j);
        }

        // packed u64 table, 4 shifted copies: tabc[r*185+m] = entries p=4m+r..+3
        for (int idx = tid; idx < 740; idx += THREADS) {
            int r = idx / 185, m = idx - r * 185;
            int p = 4 * m + r;                   // p <= 739
            int i = 0, rem = p;
            while (rem >= FN - 1 - i) { rem -= FN - 1 - i; i++; }
            int j = i + 1 + rem;
            unsigned long long e = 0;
            #pragma unroll
            for (int k = 0; k < 4; k++) {        // p+3 may exceed 740: stays in-bounds
                e |= (unsigned long long)tab_entry(i, j) << (16 * k);
                j++; if (j > FN - 1) { i++; j = i + 1; }
            }
            tabc[idx] = e;
        }
    }
    __syncthreads();

    // ---- Phase 2: 4-wide blocked expansion + relu ------------------------
    // warp owns c2; p0 = (27*c2)&31 gives 128B/16B aligned main region of
    // 704 elements = 176 float4 blocks (all with p<=734 -> <=2 rows/block).
    const int lane = tid & 31;
    const int wrp  = tid >> 5;
    float* outb = out + b * (long long)OUTB;

    #pragma unroll 1
    for (int cc = 0; cc < 8; cc++) {
        const int c2 = cc * 8 + wrp;
        const char* bu = (const char*)(Uc + c2 * 41);
        const char* bv = (const char*)(VI + c2 * 45);
        float* po = outb + c2 * PN;
        const int p0 = (27 * c2) & 31;

        // head: p in [0, p0)
        if (lane < p0) {
            unsigned t = tab16[lane];
            float u = *(const float*)(bu + (t & 255u));
            float v = *(const float*)(bv + (t >> 8));
            __stcs(po + lane, fmaxf(u + v, 0.f));
        }

        // main: 176 blocks of 4
        {
            const unsigned long long* tc = tabc + (p0 & 3) * 185 + (p0 >> 2);
            float* pom = po + p0;
            #pragma unroll
            for (int it = 0; it < 6; it++) {
                int bb = it * 32 + lane;
                if (bb < 176) {
                    unsigned long long t = tc[bb];
                    unsigned lo = (unsigned)t, hi = (unsigned)(t >> 32);
                    unsigned i0 = lo & 255u,         v0 = (lo >> 8) & 255u;
                    unsigned i1 = (lo >> 16) & 255u, v1 = lo >> 24;
                    unsigned i2 = hi & 255u,         v2 = (hi >> 8) & 255u;
                    unsigned i3 = (hi >> 16) & 255u, v3 = hi >> 24;
                    float uA = *(const float*)(bu + i0);
                    float uB = *(const float*)(bu + i3);
                    float4 o;
                    o.x = uA + *(const float*)(bv + v0);
                    o.y = (i1 == i0 ? uA : uB) + *(const float*)(bv + v1);
                    o.z = (i2 == i0 ? uA : uB) + *(const float*)(bv + v2);
                    o.w = uB + *(const float*)(bv + v3);
                    o.x = fmaxf(o.x, 0.f);
                    o.y = fmaxf(o.y, 0.f);
                    o.z = fmaxf(o.z, 0.f);
                    o.w = fmaxf(o.w, 0.f);
                    __stcs((float4*)(pom + 4 * bb), o);
                }
            }
        }

        // tail: p in [p0+704, 741)
        int p = p0 + 704 + lane;
        if (p < PN) {
            unsigned t = tab16[p];
            float u = *(const float*)(bu + (t & 255u));
            float v = *(const float*)(bv + (t >> 8));
            __stcs(po + p, fmaxf(u + v, 0.f));
        }
        p += 32;
        if (p < PN) {
            unsigned t = tab16[p];
            float u = *(const float*)(bu + (t & 255u));
            float v = *(const float*)(bv + (t >> 8));
            __stcs(po + p, fmaxf(u + v, 0.f));
        }
    }
}

extern "C" void kernel_launch(void* const* d_in, const int* in_sizes, int n_in,
                              void* d_out, int out_size)
{
    const float* x    = (const float*)d_in[0];
    const float* W    = (const float*)d_in[1];
    const float* bias = (const float*)d_in[2];
    float* out = (float*)d_out;

    const int B = in_sizes[0] / (FN * EN);   // 2048

    cudaFuncSetAttribute(interconv_kernel,
                         cudaFuncAttributeMaxDynamicSharedMemorySize, SMEM_BYTES);
    interconv_kernel<<<B, THREADS, SMEM_BYTES>>>(x, W, bias, out);
}

// round 6
// speedup vs baseline: 1.0597x; 1.0597x over previous
#include <cuda_runtime.h>

// InterConv: B=2048, F=39, E=64, C=64, P=741
// out[b, c*P + p] = relu( U[c][ii[p]] + V[c][jj[p]] ),  U = x@Wi^T + bias, V = x@Wj^T
//
// Grid = 2*B half-CTAs: each handles one batch b and c-range [c0, c0+32).
// 128 threads, 27.9 KB smem -> 8 CTAs/SM (finer grain halves the tail-wave idle).
//
// smem overlay (floats):
//   phase 0/1: xs [0,2624)   Wi [2624,4800)  Wj [4800,6976)     (stride 17 float4)
//   phase 2:   Uc [0,1312)   Vc [1312,2624)  tab [2624,3368)

#define FN 39
#define EN 64
#define CN 64
#define CH 32             // c per half-CTA
#define PN 741            // 39*38/2
#define OUTB (CN * PN)    // 47424 floats per batch
#define THREADS 128

#define XS_OFF  0
#define WI_OFF  2624
#define WJ_OFF  (WI_OFF + CH*68)      // 2176 floats each
#define UC_OFF  0                     // overlay after phase 1
#define VC_OFF  (CH*41)               // 1312
#define TAB_OFF (2*CH*41)             // 2624
#define SMEM_FLOATS 6976
#define SMEM_BYTES  (SMEM_FLOATS * 4)

// packed fp32x2 FMA (Blackwell; exact fp32 semantics, 2x FFMA throughput)
#define FMA_F32X2(acc, a, b) \
    asm("fma.rn.f32x2 %0, %1, %2, %0;" : "+l"(acc) : "l"(a), "l"(b))

extern __shared__ float smem[];

__global__ void __launch_bounds__(THREADS, 8)
interconv_kernel(const float* __restrict__ x,
                 const float* __restrict__ W,
                 const float* __restrict__ bias,
                 float* __restrict__ out)
{
    const int tid = threadIdx.x;
    const long long b = blockIdx.x >> 1;
    const int c0 = (blockIdx.x & 1) * CH;

    // ---- Phase 0: stage x and this CTA's half of W (float4) -------------
    {
        float4* xs4 = (float4*)(smem + XS_OFF);
        const float4* xb4 = (const float4*)(x + b * (long long)(FN * EN));
        #pragma unroll
        for (int it = 0; it < 5; it++) {
            int idx = tid + it * THREADS;
            if (idx < (FN * EN) / 4) xs4[idx] = xb4[idx];
        }
        if (tid < EN)                              // zero pad row f=39
            smem[XS_OFF + FN * EN + tid] = 0.f;

        // W gmem: [c][128] floats (k=0 -> Wi, k=1 -> Wj); smem stride 17 float4
        float4* Wi4 = (float4*)(smem + WI_OFF);
        float4* Wj4 = (float4*)(smem + WJ_OFF);
        const float4* Wg4 = (const float4*)W + (long long)c0 * 32;
        #pragma unroll
        for (int it = 0; it < 8; it++) {
            int idx = tid + it * THREADS;          // 1024 float4 total
            int c = idx >> 5, q = idx & 31;
            float4 w = Wg4[idx];
            if (q < 16) Wi4[c * 17 + q] = w;
            else        Wj4[c * 17 + (q - 16)] = w;
        }
    }
    __syncthreads();

    // ---- Phase 1: U = x @ Wi^T + b, V = x @ Wj^T  (f32x2, regs only) -----
    const int c  = tid & 31;          // local c within [0,32)
    const int fg = tid >> 5;          // 0..3

    unsigned long long au[10], av[10];
    #pragma unroll
    for (int k = 0; k < 10; k++) { au[k] = 0ull; av[k] = 0ull; }

    {
        const ulonglong2* xs2 = (const ulonglong2*)(smem + XS_OFF);   // [f][16]
        const ulonglong2* Wi2 = (const ulonglong2*)(smem + WI_OFF);   // [c][17]
        const ulonglong2* Wj2 = (const ulonglong2*)(smem + WJ_OFF);

        #pragma unroll
        for (int e4 = 0; e4 < 16; e4++) {
            ulonglong2 wi = Wi2[c * 17 + e4];
            ulonglong2 wj = Wj2[c * 17 + e4];
            #pragma unroll
            for (int k = 0; k < 10; k++) {
                ulonglong2 xv = xs2[(fg + 4 * k) * 16 + e4];  // f=39 row is zeros
                FMA_F32X2(au[k], xv.x, wi.x);
                FMA_F32X2(au[k], xv.y, wi.y);
                FMA_F32X2(av[k], xv.x, wj.x);
                FMA_F32X2(av[k], xv.y, wj.y);
            }
        }
    }
    __syncthreads();   // all xs/W reads done; safe to overlay

    // ---- Phase 1b: write Uc/Vc (transposed, stride 41) + build tab ------
    float* Uc = smem + UC_OFF;                // [32][41]
    float* Vc = smem + VC_OFF;                // [32][41]
    unsigned* tab = (unsigned*)(smem + TAB_OFF);

    {
        const float bc = __ldg(bias + c0 + c);
        #pragma unroll
        for (int k = 0; k < 10; k++) {
            int f = fg + 4 * k;               // f<=39; f=39 lands in row pad
            float ulo = __uint_as_float((unsigned)au[k]);
            float uhi = __uint_as_float((unsigned)(au[k] >> 32));
            float vlo = __uint_as_float((unsigned)av[k]);
            float vhi = __uint_as_float((unsigned)(av[k] >> 32));
            Uc[c * 41 + f] = ulo + uhi + bc;  // bias folded into U
            Vc[c * 41 + f] = vlo + vhi;
        }
        // pair table: np.triu_indices(F,1) row-major; byte offsets (i*4 | j*4<<16)
        for (int p = tid; p < PN; p += THREADS) {
            int i = 0, rem = p;
            while (rem >= FN - 1 - i) { rem -= FN - 1 - i; i++; }
            int j = i + 1 + rem;
            tab[p] = (unsigned)(i * 4) | ((unsigned)(j * 4) << 16);
        }
    }
    __syncthreads();

    // ---- Phase 2: expansion + relu, warp-per-c, aligned streaming stores -
    // global row gc = c0 + c2; p0 = (27*gc)&31 aligns the 704-elem main loop.
    const int lane = tid & 31;
    const int wrp  = tid >> 5;
    float* outb = out + b * (long long)OUTB;

    #pragma unroll 1
    for (int cc = 0; cc < 8; cc++) {
        const int c2 = cc * 4 + wrp;          // local row 0..31
        const int gc = c0 + c2;
        const char* bu = (const char*)(Uc + c2 * 41);
        const char* bv = (const char*)(Vc + c2 * 41);
        float* po = outb + gc * PN;
        const int p0 = (27 * gc) & 31;

        // head: p in [0, p0)
        if (lane < p0) {
            unsigned t = tab[lane];
            float u = *(const float*)(bu + (t & 0xFFFFu));
            float v = *(const float*)(bv + (t >> 16));
            __stcs(po + lane, fmaxf(u + v, 0.f));
        }

        const unsigned* tb = tab + p0;
        float* po2 = po + p0;

        // main: 22 full warp-iterations, immediate offsets, 128B-aligned stores
        #pragma unroll
        for (int it = 0; it < 22; it++) {
            unsigned t = tb[it * 32 + lane];
            float u = *(const float*)(bu + (t & 0xFFFFu));
            float v = *(const float*)(bv + (t >> 16));
            __stcs(po2 + it * 32 + lane, fmaxf(u + v, 0.f));
        }

        // tail: p in [p0+704, 741)
        int p = p0 + 704 + lane;
        if (p < PN) {
            unsigned t = tab[p];
            float u = *(const float*)(bu + (t & 0xFFFFu));
            float v = *(const float*)(bv + (t >> 16));
            __stcs(po + p, fmaxf(u + v, 0.f));
        }
        p += 32;
        if (p < PN) {
            unsigned t = tab[p];
            float u = *(const float*)(bu + (t & 0xFFFFu));
            float v = *(const float*)(bv + (t >> 16));
            __stcs(po + p, fmaxf(u + v, 0.f));
        }
    }
}

extern "C" void kernel_launch(void* const* d_in, const int* in_sizes, int n_in,
                              void* d_out, int out_size)
{
    const float* x    = (const float*)d_in[0];
    const float* W    = (const float*)d_in[1];
    const float* bias = (const float*)d_in[2];
    float* out = (float*)d_out;

    const int B = in_sizes[0] / (FN * EN);   // 2048

    cudaFuncSetAttribute(interconv_kernel,
                         cudaFuncAttributeMaxDynamicSharedMemorySize, SMEM_BYTES);
    interconv_kernel<<<B * 2, THREADS, SMEM_BYTES>>>(x, W, bias, out);
}

// round 7
// speedup vs baseline: 1.1331x; 1.0693x over previous
#include <cuda_runtime.h>

// InterConv: B=2048, F=39, E=64, C=64, P=741
// out[b, c*P + p] = relu( U[c][ii[p]] + V[c][jj[p]] ),  U = x@Wi^T + bias, V = x@Wj^T
//
// smem overlay (45.3 KB -> 4 CTAs/SM):
//   phase 0/1: A = xs [0,2624)     B = Wi [2624,6976) + Wj [6976,11328)
//   phase 2:   A = Uc [0,2624)     B = Vc [2624,5248) + tab [5248,5992)
//
// Phase 2 uses row-pairing: p0(c)=27c mod 32 == p0(c+32), so each warp handles
// 4 pairs {r, r+32}, preloading the 22-entry tab window into registers once
// per pair and reusing it for both rows (3 L1 wavefronts per 32 outputs).

#define FN 39
#define EN 64
#define CN 64
#define PN 741            // 39*38/2
#define OUTB (CN * PN)    // 47424 floats per batch
#define THREADS 256

#define A_OFF 0
#define B_OFF 2624
#define SMEM_FLOATS 11328
#define SMEM_BYTES  (SMEM_FLOATS * 4)

// packed fp32x2 FMA (Blackwell; exact fp32 semantics, 2x FFMA throughput)
#define FMA_F32X2(acc, a, b) \
    asm("fma.rn.f32x2 %0, %1, %2, %0;" : "+l"(acc) : "l"(a), "l"(b))

extern __shared__ float smem[];

__global__ void __launch_bounds__(THREADS, 4)
interconv_kernel(const float* __restrict__ x,
                 const float* __restrict__ W,
                 const float* __restrict__ bias,
                 float* __restrict__ out)
{
    const int tid = threadIdx.x;
    const long long b = blockIdx.x;

    // ---- Phase 0: stage x and W (float4) ---------------------------------
    {
        float4* xs4 = (float4*)(smem + A_OFF);
        const float4* xb4 = (const float4*)(x + b * (long long)(FN * EN));
        #pragma unroll
        for (int it = 0; it < 3; it++) {
            int idx = tid + it * THREADS;
            if (idx < (FN * EN) / 4) xs4[idx] = xb4[idx];
        }
        if (tid < EN)                              // zero pad row f=39
            smem[A_OFF + FN * EN + tid] = 0.f;

        // W gmem: [c][128] floats (k=0 -> Wi, k=1 -> Wj); smem stride 17 float4
        float4* Wi4 = (float4*)(smem + B_OFF);
        float4* Wj4 = Wi4 + CN * 17;
        const float4* Wg4 = (const float4*)W;
        #pragma unroll
        for (int it = 0; it < 8; it++) {
            int idx = tid + it * THREADS;          // 2048 float4 total
            int c = idx >> 5, q = idx & 31;
            float4 w = Wg4[idx];
            if (q < 16) Wi4[c * 17 + q] = w;
            else        Wj4[c * 17 + (q - 16)] = w;
        }
    }
    __syncthreads();

    // ---- Phase 1: U = x @ Wi^T + b, V = x @ Wj^T  (f32x2, regs only) -----
    const int c  = tid & 63;
    const int fg = tid >> 6;

    unsigned long long au[10], av[10];
    #pragma unroll
    for (int k = 0; k < 10; k++) { au[k] = 0ull; av[k] = 0ull; }

    {
        const ulonglong2* xs2 = (const ulonglong2*)(smem + A_OFF);   // [f][16]
        const ulonglong2* Wi2 = (const ulonglong2*)(smem + B_OFF);   // [c][17]
        const ulonglong2* Wj2 = Wi2 + CN * 17;

        #pragma unroll
        for (int e4 = 0; e4 < 16; e4++) {
            ulonglong2 wi = Wi2[c * 17 + e4];
            ulonglong2 wj = Wj2[c * 17 + e4];
            #pragma unroll
            for (int k = 0; k < 10; k++) {
                ulonglong2 xv = xs2[(fg + 4 * k) * 16 + e4];  // f=39 row is zeros
                FMA_F32X2(au[k], xv.x, wi.x);
                FMA_F32X2(au[k], xv.y, wi.y);
                FMA_F32X2(av[k], xv.x, wj.x);
                FMA_F32X2(av[k], xv.y, wj.y);
            }
        }
    }
    __syncthreads();   // all xs/W reads done; safe to overlay

    // ---- Phase 1b: write Uc/Vc (transposed, stride 41) + build tab ------
    float* Uc = smem + A_OFF;                 // [c][41]
    float* Vc = smem + B_OFF;                 // [c][41]
    unsigned* tab = (unsigned*)(smem + B_OFF + CN * 41);

    {
        const float bc = __ldg(bias + c);
        #pragma unroll
        for (int k = 0; k < 10; k++) {
            int f = fg + 4 * k;               // f<=39; f=39 lands in row pad
            float ulo = __uint_as_float((unsigned)au[k]);
            float uhi = __uint_as_float((unsigned)(au[k] >> 32));
            float vlo = __uint_as_float((unsigned)av[k]);
            float vhi = __uint_as_float((unsigned)(av[k] >> 32));
            Uc[c * 41 + f] = ulo + uhi + bc;  // bias folded into U
            Vc[c * 41 + f] = vlo + vhi;
        }
        // pair table: np.triu_indices(F,1) row-major; byte offsets (i*4 | j*4<<16)
        for (int p = tid; p < PN; p += THREADS) {
            int i = 0, rem = p;
            while (rem >= FN - 1 - i) { rem -= FN - 1 - i; i++; }
            int j = i + 1 + rem;
            tab[p] = (unsigned)(i * 4) | ((unsigned)(j * 4) << 16);
        }
    }
    __syncthreads();

    // ---- Phase 2: expansion + relu, paired rows, register-cached tab -----
    const int lane = tid & 31;
    const int wrp  = tid >> 5;
    float* outb = out + b * (long long)OUTB;

    #pragma unroll 1
    for (int k = 0; k < 4; k++) {
        const int r  = wrp * 4 + k;           // rows r and r+32 share p0
        const int p0 = (27 * r) & 31;

        // preload the 22-entry aligned tab window into registers
        unsigned tw[22];
        {
            const unsigned* tb = tab + p0 + lane;
            #pragma unroll
            for (int it = 0; it < 22; it++) tw[it] = tb[it * 32];
        }

        #pragma unroll
        for (int h = 0; h < 2; h++) {
            const int gc = r + 32 * h;
            const char* bu = (const char*)(Uc + gc * 41);
            const char* bv = (const char*)(Vc + gc * 41);
            float* po = outb + gc * PN;

            // head: p in [0, p0)
            if (lane < p0) {
                unsigned t = tab[lane];
                float u = *(const float*)(bu + (t & 0xFFFFu));
                float v = *(const float*)(bv + (t >> 16));
                __stcs(po + lane, fmaxf(u + v, 0.f));
            }

            // main: 22 full warp-iterations, register tab, 128B-aligned stores
            float* po2 = po + p0;
            #pragma unroll
            for (int it = 0; it < 22; it++) {
                unsigned t = tw[it];
                float u = *(const float*)(bu + (t & 0xFFFFu));
                float v = *(const float*)(bv + (t >> 16));
                __stcs(po2 + it * 32 + lane, fmaxf(u + v, 0.f));
            }

            // tail: p in [p0+704, 741)
            int p = p0 + 704 + lane;
            if (p < PN) {
                unsigned t = tab[p];
                float u = *(const float*)(bu + (t & 0xFFFFu));
                float v = *(const float*)(bv + (t >> 16));
                __stcs(po + p, fmaxf(u + v, 0.f));
            }
            p += 32;
            if (p < PN) {
                unsigned t = tab[p];
                float u = *(const float*)(bu + (t & 0xFFFFu));
                float v = *(const float*)(bv + (t >> 16));
                __stcs(po + p, fmaxf(u + v, 0.f));
            }
        }
    }
}

extern "C" void kernel_launch(void* const* d_in, const int* in_sizes, int n_in,
                              void* d_out, int out_size)
{
    const float* x    = (const float*)d_in[0];
    const float* W    = (const float*)d_in[1];
    const float* bias = (const float*)d_in[2];
    float* out = (float*)d_out;

    const int B = in_sizes[0] / (FN * EN);   // 2048

    cudaFuncSetAttribute(interconv_kernel,
                         cudaFuncAttributeMaxDynamicSharedMemorySize, SMEM_BYTES);
    interconv_kernel<<<B, THREADS, SMEM_BYTES>>>(x, W, bias, out);
}